// round 1
// baseline (speedup 1.0000x reference)
#include <cuda_runtime.h>
#include <cuda_bf16.h>
#include <math_constants.h>

// ---------------------------------------------------------------------------
// Problem constants (fixed shapes per reference)
// ---------------------------------------------------------------------------
#define BATCH   4
#define SEQ     2048
#define DMODEL  1024
#define NHEADS  16
#define HDIM    64
#define MROWS   (BATCH * SEQ)       // 8192

// ---------------------------------------------------------------------------
// Scratch (static device globals -- allocation-free rule)
// ---------------------------------------------------------------------------
__device__ float g_Q[BATCH * NHEADS * SEQ * HDIM];   // [B,H,S,d]
__device__ float g_K[BATCH * NHEADS * SEQ * HDIM];
__device__ float g_V[BATCH * NHEADS * SEQ * HDIM];
__device__ float g_Z[MROWS * DMODEL];                // [B,S,H*d]

// ---------------------------------------------------------------------------
// SGEMM: C = A[M,K] @ W[K,N] + bias  (fp32, 128x128x8 tiles, 256 thr, 8x8)
// MODE 0: C row-major [M,N]
// MODE 1: permute to [B,H,S,d]: row=(b,s), col=(h,d)
// ---------------------------------------------------------------------------
template <int MODE>
__global__ void __launch_bounds__(256)
sgemm_bias(const float* __restrict__ A, const float* __restrict__ W,
           const float* __restrict__ bias, float* __restrict__ C,
           int M, int N, int K)
{
    constexpr int BM = 128, BN = 128, BK = 8;
    __shared__ float As[BK][BM];
    __shared__ float Bs[BK][BN];

    const int t  = threadIdx.x;
    const int m0 = blockIdx.y * BM;
    const int n0 = blockIdx.x * BN;
    const int ty = t >> 4;        // 0..15
    const int tx = t & 15;        // 0..15

    const int rowA = t >> 1;              // 0..127
    const int colA = (t & 1) * 4;         // 0 or 4
    const int rowB = t >> 5;              // 0..7
    const int colB = (t & 31) * 4;        // 0..124

    const float* Aptr = A + (long)(m0 + rowA) * K + colA;
    const float* Wptr = W + (long)rowB * N + n0 + colB;

    float acc[8][8];
    #pragma unroll
    for (int i = 0; i < 8; i++)
        #pragma unroll
        for (int j = 0; j < 8; j++) acc[i][j] = 0.f;

    for (int k0 = 0; k0 < K; k0 += BK) {
        float4 av = *(const float4*)(Aptr + k0);
        float4 wv = *(const float4*)(Wptr + (long)k0 * N);

        As[colA + 0][rowA] = av.x;
        As[colA + 1][rowA] = av.y;
        As[colA + 2][rowA] = av.z;
        As[colA + 3][rowA] = av.w;
        *(float4*)&Bs[rowB][colB] = wv;
        __syncthreads();

        #pragma unroll
        for (int k = 0; k < BK; k++) {
            float a[8], b[8];
            *(float4*)&a[0] = *(const float4*)&As[k][ty * 8];
            *(float4*)&a[4] = *(const float4*)&As[k][ty * 8 + 4];
            *(float4*)&b[0] = *(const float4*)&Bs[k][tx * 8];
            *(float4*)&b[4] = *(const float4*)&Bs[k][tx * 8 + 4];
            #pragma unroll
            for (int i = 0; i < 8; i++)
                #pragma unroll
                for (int j = 0; j < 8; j++)
                    acc[i][j] = fmaf(a[i], b[j], acc[i][j]);
        }
        __syncthreads();
    }

    // epilogue
    #pragma unroll
    for (int i = 0; i < 8; i++) {
        const int row = m0 + ty * 8 + i;
        #pragma unroll
        for (int jq = 0; jq < 2; jq++) {
            const int col = n0 + tx * 8 + jq * 4;
            float4 o;
            o.x = acc[i][jq * 4 + 0] + bias[col + 0];
            o.y = acc[i][jq * 4 + 1] + bias[col + 1];
            o.z = acc[i][jq * 4 + 2] + bias[col + 2];
            o.w = acc[i][jq * 4 + 3] + bias[col + 3];
            if (MODE == 0) {
                *(float4*)&C[(long)row * N + col] = o;
            } else {
                const int b = row >> 11;      // row / SEQ
                const int s = row & 2047;     // row % SEQ
                const int h = col >> 6;       // col / HDIM
                const int d = col & 63;       // col % HDIM
                *(float4*)&C[(((long)(b * NHEADS + h)) * SEQ + s) * HDIM + d] = o;
            }
        }
    }
}

// ---------------------------------------------------------------------------
// Flash attention (fp32): one CTA = (batch b, head h, 64 q-rows)
// 256 threads as 16x16 grid; each thread owns a 4x4 tile of the 64x64 score
// block and a 4(row)x4(d) tile of the output accumulator.
// Shared tiles (stride 68 to dodge bank conflicts):
//   Qt [k][q]  (transposed)  -- persistent
//   Kt [k][key](transposed)  -- reused as Pt[j][q] after scores are consumed
//   Vs [j][d]  (row-major)
// ---------------------------------------------------------------------------
#define AT_LD 68
#define ATTN_SMEM (3 * 64 * AT_LD * 4)

__global__ void __launch_bounds__(256)
attn_kernel(const float* __restrict__ Q, const float* __restrict__ K,
            const float* __restrict__ V, float* __restrict__ Z)
{
    extern __shared__ float sm[];
    float* Qt = sm;
    float* Kt = sm + 64 * AT_LD;   // doubles as Pt
    float* Vs = sm + 2 * 64 * AT_LD;

    const int t  = threadIdx.x;
    const int qb = blockIdx.x;     // 0..31
    const int h  = blockIdx.y;     // 0..15
    const int b  = blockIdx.z;     // 0..3
    const int ty = t >> 4;         // 0..15 -> q rows ty*4..ty*4+3
    const int tx = t & 15;         // 0..15 -> keys/d cols tx*4..tx*4+3

    const long base = ((long)(b * NHEADS + h)) * SEQ * HDIM;

    // ---- load Q tile transposed: Qt[k][q] ----
    {
        const int r  = t >> 2;          // 0..63 (q row)
        const int c0 = (t & 3) * 16;    // 0,16,32,48 (k col)
        const float* gq = Q + base + (long)(qb * 64 + r) * HDIM + c0;
        #pragma unroll
        for (int u = 0; u < 4; u++) {
            float4 v = *(const float4*)(gq + u * 4);
            Qt[(c0 + u * 4 + 0) * AT_LD + r] = v.x;
            Qt[(c0 + u * 4 + 1) * AT_LD + r] = v.y;
            Qt[(c0 + u * 4 + 2) * AT_LD + r] = v.z;
            Qt[(c0 + u * 4 + 3) * AT_LD + r] = v.w;
        }
    }

    float o[4][4];
    float mrow[4], lrow[4];
    #pragma unroll
    for (int i = 0; i < 4; i++) {
        mrow[i] = -CUDART_INF_F;
        lrow[i] = 0.f;
        #pragma unroll
        for (int c = 0; c < 4; c++) o[i][c] = 0.f;
    }

    for (int kb = 0; kb < SEQ / 64; kb++) {
        __syncthreads();   // prior PV reads of Kt(Pt)/Vs complete

        // ---- load K (transposed) and V (row-major) tiles ----
        {
            const int r  = t >> 2;
            const int c0 = (t & 3) * 16;
            const float* gk = K + base + (long)(kb * 64 + r) * HDIM + c0;
            const float* gv = V + base + (long)(kb * 64 + r) * HDIM + c0;
            #pragma unroll
            for (int u = 0; u < 4; u++) {
                float4 kv = *(const float4*)(gk + u * 4);
                Kt[(c0 + u * 4 + 0) * AT_LD + r] = kv.x;
                Kt[(c0 + u * 4 + 1) * AT_LD + r] = kv.y;
                Kt[(c0 + u * 4 + 2) * AT_LD + r] = kv.z;
                Kt[(c0 + u * 4 + 3) * AT_LD + r] = kv.w;
                float4 vv = *(const float4*)(gv + u * 4);
                *(float4*)&Vs[r * AT_LD + c0 + u * 4] = vv;
            }
        }
        __syncthreads();

        // ---- scores: S = Q @ K^T (64x64x64 mini-GEMM) ----
        float s[4][4];
        #pragma unroll
        for (int i = 0; i < 4; i++)
            #pragma unroll
            for (int j = 0; j < 4; j++) s[i][j] = 0.f;

        #pragma unroll 8
        for (int k = 0; k < HDIM; k++) {
            float4 a  = *(const float4*)&Qt[k * AT_LD + ty * 4];
            float4 kk = *(const float4*)&Kt[k * AT_LD + tx * 4];
            float av[4] = {a.x, a.y, a.z, a.w};
            float bv[4] = {kk.x, kk.y, kk.z, kk.w};
            #pragma unroll
            for (int i = 0; i < 4; i++)
                #pragma unroll
                for (int j = 0; j < 4; j++)
                    s[i][j] = fmaf(av[i], bv[j], s[i][j]);
        }

        // ---- online softmax (rows reduced across the 16 tx lanes) ----
        float alpha[4];
        #pragma unroll
        for (int i = 0; i < 4; i++) {
            #pragma unroll
            for (int j = 0; j < 4; j++) s[i][j] *= 0.125f;  // 1/sqrt(64)
            float mx = fmaxf(fmaxf(s[i][0], s[i][1]), fmaxf(s[i][2], s[i][3]));
            #pragma unroll
            for (int msk = 1; msk < 16; msk <<= 1)
                mx = fmaxf(mx, __shfl_xor_sync(0xffffffffu, mx, msk));
            const float mnew = fmaxf(mrow[i], mx);
            alpha[i] = __expf(mrow[i] - mnew);
            float sum = 0.f;
            #pragma unroll
            for (int j = 0; j < 4; j++) {
                s[i][j] = __expf(s[i][j] - mnew);
                sum += s[i][j];
            }
            #pragma unroll
            for (int msk = 1; msk < 16; msk <<= 1)
                sum += __shfl_xor_sync(0xffffffffu, sum, msk);
            lrow[i] = lrow[i] * alpha[i] + sum;
            mrow[i] = mnew;
            #pragma unroll
            for (int c = 0; c < 4; c++) o[i][c] *= alpha[i];
        }

        __syncthreads();   // all score reads of Kt done -> safe to overwrite

        // ---- store P transposed into Kt buffer: Pt[j][q] ----
        #pragma unroll
        for (int j = 0; j < 4; j++)
            #pragma unroll
            for (int i = 0; i < 4; i++)
                Kt[(tx * 4 + j) * AT_LD + ty * 4 + i] = s[i][j];
        __syncthreads();

        // ---- O += P @ V (64x64x64 mini-GEMM) ----
        #pragma unroll 8
        for (int j = 0; j < 64; j++) {
            float4 p  = *(const float4*)&Kt[j * AT_LD + ty * 4];
            float4 vv = *(const float4*)&Vs[j * AT_LD + tx * 4];
            float pv[4] = {p.x, p.y, p.z, p.w};
            float vw[4] = {vv.x, vv.y, vv.z, vv.w};
            #pragma unroll
            for (int i = 0; i < 4; i++)
                #pragma unroll
                for (int c = 0; c < 4; c++)
                    o[i][c] = fmaf(pv[i], vw[c], o[i][c]);
        }
    }

    // ---- finalize + write Z in [B,S,H*d] layout ----
    #pragma unroll
    for (int i = 0; i < 4; i++) {
        const float inv = 1.f / lrow[i];
        const int row = qb * 64 + ty * 4 + i;
        float4 ov;
        ov.x = o[i][0] * inv;
        ov.y = o[i][1] * inv;
        ov.z = o[i][2] * inv;
        ov.w = o[i][3] * inv;
        *(float4*)&Z[((long)(b * SEQ + row)) * DMODEL + h * HDIM + tx * 4] = ov;
    }
}

// ---------------------------------------------------------------------------
// Host launcher
// ---------------------------------------------------------------------------
extern "C" void kernel_launch(void* const* d_in, const int* in_sizes, int n_in,
                              void* d_out, int out_size)
{
    const float* query = (const float*)d_in[0];
    const float* key   = (const float*)d_in[1];
    const float* value = (const float*)d_in[2];
    const float* Wq    = (const float*)d_in[3];
    const float* bq    = (const float*)d_in[4];
    const float* Wk    = (const float*)d_in[5];
    const float* bk    = (const float*)d_in[6];
    const float* Wv    = (const float*)d_in[7];
    const float* bv    = (const float*)d_in[8];
    const float* Wo    = (const float*)d_in[9];
    const float* bo    = (const float*)d_in[10];
    float* out = (float*)d_out;

    float *Qp, *Kp, *Vp, *Zp;
    cudaGetSymbolAddress((void**)&Qp, g_Q);
    cudaGetSymbolAddress((void**)&Kp, g_K);
    cudaGetSymbolAddress((void**)&Vp, g_V);
    cudaGetSymbolAddress((void**)&Zp, g_Z);

    const dim3 gg(DMODEL / 128, MROWS / 128);  // (8, 64)
    const dim3 gb(256);

    // QKV projections -> [B,H,S,d] scratch
    sgemm_bias<1><<<gg, gb>>>(query, Wq, bq, Qp, MROWS, DMODEL, DMODEL);
    sgemm_bias<1><<<gg, gb>>>(key,   Wk, bk, Kp, MROWS, DMODEL, DMODEL);
    sgemm_bias<1><<<gg, gb>>>(value, Wv, bv, Vp, MROWS, DMODEL, DMODEL);

    // Attention -> Z [B,S,H*d]
    cudaFuncSetAttribute(attn_kernel,
                         cudaFuncAttributeMaxDynamicSharedMemorySize,
                         ATTN_SMEM);
    attn_kernel<<<dim3(SEQ / 64, NHEADS, BATCH), 256, ATTN_SMEM>>>(Qp, Kp, Vp, Zp);

    // Output projection -> d_out
    sgemm_bias<0><<<gg, gb>>>(Zp, Wo, bo, out, MROWS, DMODEL, DMODEL);
}